// round 1
// baseline (speedup 1.0000x reference)
#include <cuda_runtime.h>
#include <math_constants.h>
#include <cstddef>

// Problem shape (fixed by the reference): B=4, H=16, S=1024, D=128, fp32.
constexpr int Bn = 4, Hn = 16, Sn = 1024, Dn = 128;
constexpr int TQ = 32;      // q rows per CTA
constexpr int KT = 128;     // k/v rows per smem tile
constexpr int THREADS = 256;

constexpr int QS_ELEMS   = Dn * TQ;          // q tile, d-major [128][32]
constexpr int KV_STRIDE  = 132;              // padded row stride (conflict-free LDS.128)
constexpr int KV_ELEMS   = KT * KV_STRIDE;   // k/v tile [128][132]
constexpr int SS_ELEMS   = TQ * Sn;          // score rows [32][1024]
constexpr size_t SMEM_BYTES = (size_t)(QS_ELEMS + KV_ELEMS + SS_ELEMS) * sizeof(float); // 215040 B

__global__ __launch_bounds__(THREADS, 1)
void sdpa_fused_kernel(const float* __restrict__ q,
                       const float* __restrict__ k,
                       const float* __restrict__ v,
                       const int*   __restrict__ mask,
                       float* __restrict__ ctx,    // may be null
                       float* __restrict__ attn)   // may be null
{
    extern __shared__ float sm[];
    float* q_s  = sm;                         // [d][qrow]  128x32
    float* kv_s = sm + QS_ELEMS;              // k: [d][krow] 128x132 ; v: [vrow][d] 128x132
    float* s_s  = sm + QS_ELEMS + KV_ELEMS;   // [qrow][1024]

    const int bh  = blockIdx.y;               // 0..63
    const int b   = bh >> 4;
    const int q0  = blockIdx.x * TQ;
    const int tid = threadIdx.x;
    const int ty  = tid >> 5;                 // 0..7  (warp id) -> q-row group of 4
    const int tx  = tid & 31;                 // 0..31 -> col group of 4

    const size_t bh_off = (size_t)bh * Sn * Dn;
    const float* qg = q + bh_off + (size_t)q0 * Dn;

    // Load Q tile transposed (d-major). 32-way store conflicts, but tiny one-time cost.
    for (int i = tid; i < TQ * Dn; i += THREADS) {
        int row = i >> 7, d = i & 127;
        q_s[d * TQ + row] = qg[(size_t)row * Dn + d];
    }

    const float scale = 0.08838834764831845f;   // 1/sqrt(128)

    // ---------------- Phase 1: scores = scale * Q K^T  (per k-tile of 128 cols) ---------
    for (int kt = 0; kt < Sn / KT; kt++) {
        const float* kg = k + bh_off + (size_t)kt * KT * Dn;
        __syncthreads();   // protect kv_s from previous iteration readers (and q_s on iter 0)
        for (int i = tid; i < KT * Dn; i += THREADS) {
            int row = i >> 7, d = i & 127;
            kv_s[d * KV_STRIDE + row] = kg[i];  // transposed store (4-way conflict, cheap)
        }
        __syncthreads();

        float acc[4][4] = {};
        #pragma unroll 4
        for (int d = 0; d < Dn; d++) {
            float4 rq = *(const float4*)&q_s[d * TQ + ty * 4];         // warp-broadcast
            float4 rk = *(const float4*)&kv_s[d * KV_STRIDE + tx * 4]; // conflict-free
            float aq[4] = {rq.x, rq.y, rq.z, rq.w};
            float ak[4] = {rk.x, rk.y, rk.z, rk.w};
            #pragma unroll
            for (int i = 0; i < 4; i++)
                #pragma unroll
                for (int j = 0; j < 4; j++)
                    acc[i][j] = fmaf(aq[i], ak[j], acc[i][j]);
        }
        #pragma unroll
        for (int i = 0; i < 4; i++) {
            float4 o = make_float4(acc[i][0] * scale, acc[i][1] * scale,
                                   acc[i][2] * scale, acc[i][3] * scale);
            *(float4*)&s_s[(ty * 4 + i) * Sn + kt * KT + tx * 4] = o;
        }
    }
    __syncthreads();

    // ---------------- Softmax over full rows (exact, in smem), stream attn out ---------
    const int* mbase = mask + ((size_t)b * Sn + q0) * Sn;   // mask [B,1,S,S]
    for (int r = ty; r < TQ; r += 8) {
        float* srow = &s_s[r * Sn];
        const int* mrow = mbase + (size_t)r * Sn;
        float mx = -CUDART_INF_F;
        for (int c = tx; c < Sn; c += 32) {
            float sv = srow[c];
            if (mrow[c] == 0) sv = -1.0e9f;   // NEG_INF per reference (post-scale constant)
            srow[c] = sv;
            mx = fmaxf(mx, sv);
        }
        #pragma unroll
        for (int off = 16; off > 0; off >>= 1)
            mx = fmaxf(mx, __shfl_xor_sync(0xffffffffu, mx, off));
        float sum = 0.f;
        for (int c = tx; c < Sn; c += 32) {
            float e = __expf(srow[c] - mx);
            srow[c] = e;
            sum += e;
        }
        #pragma unroll
        for (int off = 16; off > 0; off >>= 1)
            sum += __shfl_xor_sync(0xffffffffu, sum, off);
        float inv = 1.0f / sum;
        float* arow = attn ? (attn + ((size_t)bh * Sn + q0 + r) * Sn) : nullptr;
        for (int c = tx; c < Sn; c += 32) {
            float p = srow[c] * inv;
            srow[c] = p;
            if (arow) arow[c] = p;
        }
    }

    // ---------------- Phase 2: context = P V  --------------------------------------
    float acc2[4][4] = {};
    for (int vt = 0; vt < Sn / KT; vt++) {
        const float* vg = v + bh_off + (size_t)vt * KT * Dn;
        __syncthreads();   // also orders softmax s_s writes before P reads below
        for (int i = tid; i < KT * Dn; i += THREADS) {
            kv_s[(i >> 7) * KV_STRIDE + (i & 127)] = vg[i];   // natural [row][d]
        }
        __syncthreads();
        #pragma unroll 2
        for (int r = 0; r < KT; r += 4) {
            float4 rp[4];
            #pragma unroll
            for (int i = 0; i < 4; i++)
                rp[i] = *(const float4*)&s_s[(ty * 4 + i) * Sn + vt * KT + r]; // broadcast
            #pragma unroll
            for (int rr = 0; rr < 4; rr++) {
                float4 rv = *(const float4*)&kv_s[(r + rr) * KV_STRIDE + tx * 4];
                #pragma unroll
                for (int i = 0; i < 4; i++) {
                    float p = (&rp[i].x)[rr];
                    acc2[i][0] = fmaf(p, rv.x, acc2[i][0]);
                    acc2[i][1] = fmaf(p, rv.y, acc2[i][1]);
                    acc2[i][2] = fmaf(p, rv.z, acc2[i][2]);
                    acc2[i][3] = fmaf(p, rv.w, acc2[i][3]);
                }
            }
        }
    }
    if (ctx) {
        #pragma unroll
        for (int i = 0; i < 4; i++) {
            float4 o = make_float4(acc2[i][0], acc2[i][1], acc2[i][2], acc2[i][3]);
            *(float4*)&ctx[bh_off + (size_t)(q0 + ty * 4 + i) * Dn + tx * 4] = o;
        }
    }
}

extern "C" void kernel_launch(void* const* d_in, const int* in_sizes, int n_in,
                              void* d_out, int out_size)
{
    const float* q    = (const float*)d_in[0];
    const float* k    = (const float*)d_in[1];
    const float* v    = (const float*)d_in[2];
    const int*   mask = (const int*)d_in[3];

    const size_t CTX = (size_t)Bn * Hn * Sn * Dn;   //  8,388,608
    const size_t ATT = (size_t)Bn * Hn * Sn * Sn;   // 67,108,864

    float* ctx  = (float*)d_out;
    float* attn = nullptr;
    size_t osz = (size_t)out_size;
    if (osz >= CTX + ATT) {
        attn = (float*)d_out + CTX;           // outputs concatenated: (context, attn)
    } else if (osz == ATT) {
        attn = (float*)d_out;                 // attn-only fallback
        ctx = nullptr;
    } // else: context-only — attn stays null

    cudaFuncSetAttribute(sdpa_fused_kernel,
                         cudaFuncAttributeMaxDynamicSharedMemorySize, (int)SMEM_BYTES);

    dim3 grid(Sn / TQ, Bn * Hn);   // 32 x 64 = 2048 CTAs
    sdpa_fused_kernel<<<grid, THREADS, SMEM_BYTES>>>(q, k, v, mask, ctx, attn);
}